// round 1
// baseline (speedup 1.0000x reference)
#include <cuda_runtime.h>
#include <cstddef>

// ---------------------------------------------------------------------------
// Fused 2-block ST-GCN + FC, fp32.
//   x: [64,512,2,21,2]  ->  out: [64,512,2,64]
// Kernel 1 (prep): fold BN into tcn/res weights, build normalized A,
//                  transpose fc_w -> [672][64].
// Kernel 2 (main): grid (16 chunks, 2 hands, 64 batch); CTA = 512 threads
//   (16 warps, lane = output channel). Smem-staged pipeline with 2-step
//   temporal halo per chunk:
//     A: gcn0 out (36 slots) -> B: tcn0+bn+res+relu (34) ->
//     C: gcn1 out (34, aliases A) -> D: tcn1+bn+res+relu (32, regs) ->
//     E: fc (fc_w streamed through smem in 56-wide K chunks).
// ---------------------------------------------------------------------------

#define TLEN  512
#define NV    21
#define VP    22          // padded V stride (even -> float2 loads)
#define NC    32
#define NOUT  64
#define FCK   (NC*NV)     // 672
#define TC    32
#define NCHUNK (TLEN/TC)  // 16
#define SLOTA (TC+4)      // 36
#define SLOTB (TC+2)      // 34
#define NWARP 16
#define NTHR  (NWARP*32)
#define IC    56          // fc K-chunk (672 = 12*56)
#define ICP   60          // padded chunk row stride

// smem layout (floats)
#define OFF_A    0
#define SZ_A     (SLOTA*NC*VP)            // 25344
#define OFF_B    (OFF_A+SZ_A)
#define SZ_B     (SLOTB*NC*VP)            // 23936
#define OFF_AS   (OFF_B+SZ_B)
#define SZ_AS    464                      // A matrix 21x22 (+pad)
#define OFF_TW   (OFF_AS+SZ_AS)
#define SZ_TW    4352                     // tcn weights (3072) / fc chunk (64*60)
#define OFF_W1   (OFF_TW+SZ_TW)
#define SZ_W1    (NC*NC)                  // 1024
#define OFF_PP   (OFF_W1+SZ_W1)
#define SZ_PP    352
#define SMEM_FLOATS (OFF_PP+SZ_PP)
#define SMEM_BYTES  (SMEM_FLOATS*4)       // 221,888 B

// ------------------------- folded parameter storage -------------------------
__device__ float g_A[NV*VP];
__device__ float g_gw0[2*NC];     // [ci][o]
__device__ float g_gb0[NC];
__device__ float g_tw0[NC*3*NC];  // [i][k][o], BN-scaled
__device__ float g_tb0[NC];
__device__ float g_rw[2*NC];      // [ci][o], BN-scaled
__device__ float g_rb[NC];
__device__ float g_w1[NC*NC];     // [i][o]
__device__ float g_gb1[NC];
__device__ float g_tw1[NC*3*NC];  // [i][k][o], BN-scaled
__device__ float g_tb1[NC];
__device__ float g_fcwt[FCK*NOUT];// [i][j]
__device__ float g_fcb[NOUT];

__global__ void prep_kernel(
    const float* __restrict__ gcn_w0, const float* __restrict__ gcn_b0,
    const float* __restrict__ tcn_w0, const float* __restrict__ tcn_b0,
    const float* __restrict__ bn_g0,  const float* __restrict__ bn_b0,
    const float* __restrict__ bn_m0,  const float* __restrict__ bn_v0,
    const float* __restrict__ res_w,  const float* __restrict__ res_b,
    const float* __restrict__ res_bn_g, const float* __restrict__ res_bn_b,
    const float* __restrict__ res_bn_m, const float* __restrict__ res_bn_v,
    const float* __restrict__ gcn_w1, const float* __restrict__ gcn_b1,
    const float* __restrict__ tcn_w1, const float* __restrict__ tcn_b1,
    const float* __restrict__ bn_g1,  const float* __restrict__ bn_b1,
    const float* __restrict__ bn_m1,  const float* __restrict__ bn_v1,
    const float* __restrict__ fc_w,   const float* __restrict__ fc_b)
{
    int tid = threadIdx.x;
    if (tid == 0) {
        // build normalized adjacency A = D^-1/2 (Adj + I) D^-1/2
        float Ad[NV][NV];
        for (int i = 0; i < NV; i++)
            for (int j = 0; j < NV; j++)
                Ad[i][j] = (i == j) ? 1.f : 0.f;
        const int conn[20][2] = {{0,1},{1,2},{2,3},{3,4},{0,5},{5,6},{6,7},{7,8},
                                 {0,9},{9,10},{10,11},{11,12},{0,13},{13,14},{14,15},
                                 {15,16},{0,17},{17,18},{18,19},{19,20}};
        for (int e = 0; e < 20; e++) {
            Ad[conn[e][0]][conn[e][1]] = 1.f;
            Ad[conn[e][1]][conn[e][0]] = 1.f;
        }
        float d[NV];
        for (int i = 0; i < NV; i++) {
            float s = 0.f;
            for (int j = 0; j < NV; j++) s += Ad[i][j];
            d[i] = rsqrtf(s);
        }
        for (int i = 0; i < NV; i++) {
            for (int j = 0; j < NV; j++) g_A[i*VP + j] = d[i] * Ad[i][j] * d[j];
            g_A[i*VP + 21] = 0.f;
        }
    }
    for (int o = tid; o < NC; o += blockDim.x) {
        float s0 = bn_g0[o] * rsqrtf(bn_v0[o] + 1e-5f);
        g_gb0[o] = gcn_b0[o];
        g_gw0[0*NC + o] = gcn_w0[o*2 + 0];
        g_gw0[1*NC + o] = gcn_w0[o*2 + 1];
        for (int i = 0; i < NC; i++)
            for (int k = 0; k < 3; k++)
                g_tw0[(i*3 + k)*NC + o] = tcn_w0[(o*NC + i)*3 + k] * s0;
        g_tb0[o] = (tcn_b0[o] - bn_m0[o]) * s0 + bn_b0[o];

        float sr = res_bn_g[o] * rsqrtf(res_bn_v[o] + 1e-5f);
        g_rw[0*NC + o] = res_w[o*2 + 0] * sr;
        g_rw[1*NC + o] = res_w[o*2 + 1] * sr;
        g_rb[o] = (res_b[o] - res_bn_m[o]) * sr + res_bn_b[o];

        float s1 = bn_g1[o] * rsqrtf(bn_v1[o] + 1e-5f);
        g_gb1[o] = gcn_b1[o];
        for (int i = 0; i < NC; i++) g_w1[i*NC + o] = gcn_w1[o*NC + i];
        for (int i = 0; i < NC; i++)
            for (int k = 0; k < 3; k++)
                g_tw1[(i*3 + k)*NC + o] = tcn_w1[(o*NC + i)*3 + k] * s1;
        g_tb1[o] = (tcn_b1[o] - bn_m1[o]) * s1 + bn_b1[o];
    }
    for (int idx = tid; idx < FCK*NOUT; idx += blockDim.x) {
        int i = idx / NOUT, j = idx % NOUT;
        g_fcwt[idx] = fc_w[j*FCK + i];
    }
    for (int j = tid; j < NOUT; j += blockDim.x) g_fcb[j] = fc_b[j];
}

// ------------------------------- main kernel --------------------------------
__global__ __launch_bounds__(NTHR, 1)
void stgcn_kernel(const float* __restrict__ x, float* __restrict__ outp)
{
    extern __shared__ float smem[];
    float* bufA = smem + OFF_A;
    float* bufB = smem + OFF_B;
    float* As   = smem + OFF_AS;
    float* tWs  = smem + OFF_TW;
    float* W1s  = smem + OFF_W1;
    float* pp   = smem + OFF_PP;
    float* s_gw0 = pp;         // 64
    float* s_gb0 = pp + 64;    // 32
    float* s_tb0 = pp + 96;    // 32
    float* s_rw  = pp + 128;   // 64
    float* s_rb  = pp + 192;   // 32
    float* s_gb1 = pp + 224;   // 32
    float* s_tb1 = pp + 256;   // 32
    float* s_fcb = pp + 288;   // 64

    const int tid  = threadIdx.x;
    const int lane = tid & 31;
    const int wid  = tid >> 5;
    const int o    = lane;               // lane = output channel
    const int chunk = blockIdx.x;
    const int hand  = blockIdx.y;
    const int b     = blockIdx.z;
    const int t0    = chunk * TC;

    // load weights into smem
    for (int i = tid; i < NV*VP; i += NTHR) As[i] = g_A[i];
    for (int i = tid; i < NC*3*NC; i += NTHR) tWs[i] = g_tw0[i];
    for (int i = tid; i < NC*NC; i += NTHR) W1s[i] = g_w1[i];
    if (tid < 64) { s_gw0[tid] = g_gw0[tid]; s_rw[tid] = g_rw[tid]; s_fcb[tid] = g_fcb[tid]; }
    if (tid < 32) {
        s_gb0[tid] = g_gb0[tid]; s_tb0[tid] = g_tb0[tid]; s_rb[tid] = g_rb[tid];
        s_gb1[tid] = g_gb1[tid]; s_tb1[tid] = g_tb1[tid];
    }
    __syncthreads();

    // sparse structure of A (hardcoded from _CONNECTIONS, fully unrolled)
    constexpr int DEG[NV] = {6,3,3,3,2,3,3,3,2,3,3,3,2,3,3,3,2,3,3,3,2};
    constexpr int NBR[NV][6] = {
        {0,1,5,9,13,17},{0,1,2,0,0,0},{1,2,3,0,0,0},{2,3,4,0,0,0},{3,4,0,0,0,0},
        {0,5,6,0,0,0},{5,6,7,0,0,0},{6,7,8,0,0,0},{7,8,0,0,0,0},
        {0,9,10,0,0,0},{9,10,11,0,0,0},{10,11,12,0,0,0},{11,12,0,0,0,0},
        {0,13,14,0,0,0},{13,14,15,0,0,0},{14,15,16,0,0,0},{15,16,0,0,0,0},
        {0,17,18,0,0,0},{17,18,19,0,0,0},{18,19,20,0,0,0},{19,20,0,0,0,0}};

    // ---------------- Stage A: gcn0 (A-mix + 2->32 channel lift + bias) -----
    {
        const float w00 = s_gw0[o], w01 = s_gw0[NC + o];
        const float gb0 = s_gb0[o];
        for (int s = wid; s < SLOTA; s += NWARP) {
            int t = t0 + s - 2;
            float* dst = bufA + (s*NC + o)*VP;
            if (t < 0 || t >= TLEN) {
                #pragma unroll
                for (int v = 0; v < VP; v++) dst[v] = 0.f;
            } else {
                const float2* xp = (const float2*)(x + ((size_t)((b*TLEN + t)*2 + hand)*NV)*2);
                float p[NV];
                #pragma unroll
                for (int u = 0; u < NV; u++) {
                    float2 xv = xp[u];
                    p[u] = w00*xv.x + w01*xv.y;
                }
                #pragma unroll
                for (int v = 0; v < NV; v++) {
                    float acc = gb0;
                    #pragma unroll
                    for (int j = 0; j < 6; j++)
                        if (j < DEG[v]) acc += As[v*VP + NBR[v][j]] * p[NBR[v][j]];
                    dst[v] = acc;
                }
                dst[21] = 0.f;
            }
        }
    }
    __syncthreads();

    // ---------------- Stage B: tcn0 + bn0 (folded) + res0 + relu ------------
    {
        const float tb0 = s_tb0[o];
        const float rw0 = s_rw[o], rw1 = s_rw[NC + o], rb = s_rb[o];
        for (int s = wid; s < SLOTB; s += NWARP) {
            int t = t0 + s - 1;
            float* dst = bufB + (s*NC + o)*VP;
            if (t < 0 || t >= TLEN) {
                #pragma unroll
                for (int v = 0; v < VP; v++) dst[v] = 0.f;
            } else {
                float2 acc[11];
                #pragma unroll
                for (int q = 0; q < 11; q++) acc[q] = make_float2(tb0, tb0);
                for (int k = 0; k < 3; k++) {
                    const float* base = bufA + (s + k)*NC*VP;
                    for (int i = 0; i < NC; i++) {
                        float w = tWs[(i*3 + k)*NC + o];
                        const float2* row = (const float2*)(base + i*VP);
                        #pragma unroll
                        for (int q = 0; q < 11; q++) {
                            float2 h = row[q];
                            acc[q].x += w*h.x; acc[q].y += w*h.y;
                        }
                    }
                }
                const float2* xp = (const float2*)(x + ((size_t)((b*TLEN + t)*2 + hand)*NV)*2);
                #pragma unroll
                for (int q = 0; q < 11; q++) {
                    int v0 = 2*q, v1 = 2*q + 1;
                    float2 xv0 = xp[v0];
                    float r0 = rb + rw0*xv0.x + rw1*xv0.y;
                    float y0 = acc[q].x + r0;
                    dst[v0] = y0 > 0.f ? y0 : 0.f;
                    if (v1 < NV) {
                        float2 xv1 = xp[v1];
                        float r1 = rb + rw0*xv1.x + rw1*xv1.y;
                        float y1 = acc[q].y + r1;
                        dst[v1] = y1 > 0.f ? y1 : 0.f;
                    } else {
                        dst[v1] = 0.f;
                    }
                }
            }
        }
    }
    __syncthreads();

    // swap in tcn1 weights (tWs region free after stage B)
    for (int i = tid; i < NC*3*NC; i += NTHR) tWs[i] = g_tw1[i];
    __syncthreads();

    // ---------------- Stage C: gcn1 (channel mix then A-mix), into bufA -----
    {
        const float gb1 = s_gb1[o];
        for (int s = wid; s < SLOTB; s += NWARP) {
            int t = t0 + s - 1;
            float* dst = bufA + (s*NC + o)*VP;   // bufC aliases bufA
            if (t < 0 || t >= TLEN) {
                #pragma unroll
                for (int v = 0; v < VP; v++) dst[v] = 0.f;
            } else {
                float2 r2[11];
                #pragma unroll
                for (int q = 0; q < 11; q++) r2[q] = make_float2(0.f, 0.f);
                const float* base = bufB + s*NC*VP;
                for (int i = 0; i < NC; i++) {
                    float w = W1s[i*NC + o];
                    const float2* row = (const float2*)(base + i*VP);
                    #pragma unroll
                    for (int q = 0; q < 11; q++) {
                        float2 h = row[q];
                        r2[q].x += w*h.x; r2[q].y += w*h.y;
                    }
                }
                float r[VP];
                #pragma unroll
                for (int q = 0; q < 11; q++) { r[2*q] = r2[q].x; r[2*q+1] = r2[q].y; }
                #pragma unroll
                for (int v = 0; v < NV; v++) {
                    float acc = gb1;
                    #pragma unroll
                    for (int j = 0; j < 6; j++)
                        if (j < DEG[v]) acc += As[v*VP + NBR[v][j]] * r[NBR[v][j]];
                    dst[v] = acc;
                }
                dst[21] = 0.f;
            }
        }
    }
    __syncthreads();

    // ---------------- Stage D: tcn1 + bn1 (folded) + identity res + relu ----
    float dreg[2][NV];
    {
        const float tb1 = s_tb1[o];
        #pragma unroll
        for (int half = 0; half < 2; half++) {
            int s = wid + half*NWARP;           // output t = t0 + s, always valid
            float2 acc[11];
            #pragma unroll
            for (int q = 0; q < 11; q++) acc[q] = make_float2(tb1, tb1);
            for (int k = 0; k < 3; k++) {
                const float* base = bufA + (s + k)*NC*VP;
                for (int i = 0; i < NC; i++) {
                    float w = tWs[(i*3 + k)*NC + o];
                    const float2* row = (const float2*)(base + i*VP);
                    #pragma unroll
                    for (int q = 0; q < 11; q++) {
                        float2 h = row[q];
                        acc[q].x += w*h.x; acc[q].y += w*h.y;
                    }
                }
            }
            const float2* rr = (const float2*)(bufB + ((s + 1)*NC + o)*VP);
            #pragma unroll
            for (int q = 0; q < 11; q++) {
                float2 res = rr[q];
                float y0 = acc[q].x + res.x;
                dreg[half][2*q] = y0 > 0.f ? y0 : 0.f;
                if (2*q + 1 < NV) {
                    float y1 = acc[q].y + res.y;
                    dreg[half][2*q + 1] = y1 > 0.f ? y1 : 0.f;
                }
            }
        }
    }
    __syncthreads();   // all reads of bufB done -> safe to overwrite with hf
    #pragma unroll
    for (int half = 0; half < 2; half++) {
        int s = wid + half*NWARP;
        float* hf = bufB + s*FCK + o*NV;   // hf layout: [slot][c*21+v], stride 672
        #pragma unroll
        for (int v = 0; v < NV; v++) hf[v] = dreg[half][v];
    }
    __syncthreads();

    // ---------------- Stage E: fc (672 -> 64), fc_w streamed via smem -------
    {
        float a00 = 0.f, a01 = 0.f, a10 = 0.f, a11 = 0.f;
        const float* hfA = bufB + wid*FCK;
        const float* hfB = bufB + (wid + NWARP)*FCK;
        for (int c0 = 0; c0 < FCK; c0 += IC) {
            // load transposed chunk: fcs[j][ii] = fcWT[c0+ii][j]
            for (int idx = tid; idx < IC*NOUT; idx += NTHR) {
                int ii = idx >> 6, j = idx & 63;
                tWs[j*ICP + ii] = g_fcwt[(c0 + ii)*NOUT + j];
            }
            __syncthreads();
            const float4* w0p = (const float4*)(tWs + lane*ICP);
            const float4* w1p = (const float4*)(tWs + (lane + 32)*ICP);
            const float4* h0p = (const float4*)(hfA + c0);
            const float4* h1p = (const float4*)(hfB + c0);
            #pragma unroll
            for (int q = 0; q < IC/4; q++) {
                float4 wa = w0p[q], wb = w1p[q], h0 = h0p[q], h1 = h1p[q];
                a00 += wa.x*h0.x + wa.y*h0.y + wa.z*h0.z + wa.w*h0.w;
                a01 += wb.x*h0.x + wb.y*h0.y + wb.z*h0.z + wb.w*h0.w;
                a10 += wa.x*h1.x + wa.y*h1.y + wa.z*h1.z + wa.w*h1.w;
                a11 += wb.x*h1.x + wb.y*h1.y + wb.z*h1.z + wb.w*h1.w;
            }
            __syncthreads();
        }
        int ta = t0 + wid, tb_ = t0 + wid + NWARP;
        float* opa = outp + ((size_t)((b*TLEN + ta)*2 + hand))*NOUT;
        opa[lane]      = a00 + s_fcb[lane];
        opa[lane + 32] = a01 + s_fcb[lane + 32];
        float* opb = outp + ((size_t)((b*TLEN + tb_)*2 + hand))*NOUT;
        opb[lane]      = a10 + s_fcb[lane];
        opb[lane + 32] = a11 + s_fcb[lane + 32];
    }
}

// ------------------------------- launch -------------------------------------
extern "C" void kernel_launch(void* const* d_in, const int* in_sizes, int n_in,
                              void* d_out, int out_size)
{
    (void)in_sizes; (void)n_in; (void)out_size;
    const float* x = (const float*)d_in[0];

    prep_kernel<<<1, 512>>>(
        (const float*)d_in[1],  (const float*)d_in[2],
        (const float*)d_in[3],  (const float*)d_in[4],
        (const float*)d_in[5],  (const float*)d_in[6],
        (const float*)d_in[7],  (const float*)d_in[8],
        (const float*)d_in[9],  (const float*)d_in[10],
        (const float*)d_in[11], (const float*)d_in[12],
        (const float*)d_in[13], (const float*)d_in[14],
        (const float*)d_in[15], (const float*)d_in[16],
        (const float*)d_in[17], (const float*)d_in[18],
        (const float*)d_in[19], (const float*)d_in[20],
        (const float*)d_in[21], (const float*)d_in[22],
        (const float*)d_in[23], (const float*)d_in[24]);

    cudaFuncSetAttribute(stgcn_kernel,
                         cudaFuncAttributeMaxDynamicSharedMemorySize, SMEM_BYTES);
    dim3 grid(NCHUNK, 2, 64);
    stgcn_kernel<<<grid, NTHR, SMEM_BYTES>>>(x, (float*)d_out);
}

// round 2
// speedup vs baseline: 1.0012x; 1.0012x over previous
#include <cuda_runtime.h>
#include <cstddef>

// ---------------------------------------------------------------------------
// Fused 2-block ST-GCN + FC, fp32.
//   x: [64,512,2,21,2]  ->  out: [64,512,2,64]
// Kernel 1 (prep): fold BN into tcn/res weights, build normalized A,
//                  transpose fc_w -> [672][64].
// Kernel 2 (main): grid (16 chunks, 2 hands, 64 batch); CTA = 512 threads
//   (16 warps, lane = output channel). Smem-staged pipeline with 2-step
//   temporal halo per chunk:
//     A: gcn0 out (36 slots) -> B: tcn0+bn+res+relu (34) ->
//     C: gcn1 out (34, aliases A) -> D: tcn1+bn+res+relu (32, regs) ->
//     E: fc (fc_w streamed through smem in 56-wide K chunks).
// ---------------------------------------------------------------------------

#define TLEN  512
#define NV    21
#define VP    22          // padded V stride (even -> float2 loads)
#define NC    32
#define NOUT  64
#define FCK   (NC*NV)     // 672
#define TC    32
#define NCHUNK (TLEN/TC)  // 16
#define SLOTA (TC+4)      // 36
#define SLOTB (TC+2)      // 34
#define NWARP 16
#define NTHR  (NWARP*32)
#define IC    56          // fc K-chunk (672 = 12*56)
#define ICP   60          // padded chunk row stride

// smem layout (floats)
#define OFF_A    0
#define SZ_A     (SLOTA*NC*VP)            // 25344
#define OFF_B    (OFF_A+SZ_A)
#define SZ_B     (SLOTB*NC*VP)            // 23936
#define OFF_AS   (OFF_B+SZ_B)
#define SZ_AS    464                      // A matrix 21x22 (+pad)
#define OFF_TW   (OFF_AS+SZ_AS)
#define SZ_TW    4352                     // tcn weights (3072) / fc chunk (64*60)
#define OFF_W1   (OFF_TW+SZ_TW)
#define SZ_W1    (NC*NC)                  // 1024
#define OFF_PP   (OFF_W1+SZ_W1)
#define SZ_PP    352
#define SMEM_FLOATS (OFF_PP+SZ_PP)
#define SMEM_BYTES  (SMEM_FLOATS*4)       // 221,888 B

// ------------------------- folded parameter storage -------------------------
__device__ float g_A[NV*VP];
__device__ float g_gw0[2*NC];     // [ci][o]
__device__ float g_gb0[NC];
__device__ float g_tw0[NC*3*NC];  // [i][k][o], BN-scaled
__device__ float g_tb0[NC];
__device__ float g_rw[2*NC];      // [ci][o], BN-scaled
__device__ float g_rb[NC];
__device__ float g_w1[NC*NC];     // [i][o]
__device__ float g_gb1[NC];
__device__ float g_tw1[NC*3*NC];  // [i][k][o], BN-scaled
__device__ float g_tb1[NC];
__device__ float g_fcwt[FCK*NOUT];// [i][j]
__device__ float g_fcb[NOUT];

__global__ void prep_kernel(
    const float* __restrict__ gcn_w0, const float* __restrict__ gcn_b0,
    const float* __restrict__ tcn_w0, const float* __restrict__ tcn_b0,
    const float* __restrict__ bn_g0,  const float* __restrict__ bn_b0,
    const float* __restrict__ bn_m0,  const float* __restrict__ bn_v0,
    const float* __restrict__ res_w,  const float* __restrict__ res_b,
    const float* __restrict__ res_bn_g, const float* __restrict__ res_bn_b,
    const float* __restrict__ res_bn_m, const float* __restrict__ res_bn_v,
    const float* __restrict__ gcn_w1, const float* __restrict__ gcn_b1,
    const float* __restrict__ tcn_w1, const float* __restrict__ tcn_b1,
    const float* __restrict__ bn_g1,  const float* __restrict__ bn_b1,
    const float* __restrict__ bn_m1,  const float* __restrict__ bn_v1,
    const float* __restrict__ fc_w,   const float* __restrict__ fc_b)
{
    int tid = threadIdx.x;
    if (tid == 0) {
        // build normalized adjacency A = D^-1/2 (Adj + I) D^-1/2
        float Ad[NV][NV];
        for (int i = 0; i < NV; i++)
            for (int j = 0; j < NV; j++)
                Ad[i][j] = (i == j) ? 1.f : 0.f;
        const int conn[20][2] = {{0,1},{1,2},{2,3},{3,4},{0,5},{5,6},{6,7},{7,8},
                                 {0,9},{9,10},{10,11},{11,12},{0,13},{13,14},{14,15},
                                 {15,16},{0,17},{17,18},{18,19},{19,20}};
        for (int e = 0; e < 20; e++) {
            Ad[conn[e][0]][conn[e][1]] = 1.f;
            Ad[conn[e][1]][conn[e][0]] = 1.f;
        }
        float d[NV];
        for (int i = 0; i < NV; i++) {
            float s = 0.f;
            for (int j = 0; j < NV; j++) s += Ad[i][j];
            d[i] = rsqrtf(s);
        }
        for (int i = 0; i < NV; i++) {
            for (int j = 0; j < NV; j++) g_A[i*VP + j] = d[i] * Ad[i][j] * d[j];
            g_A[i*VP + 21] = 0.f;
        }
    }
    for (int o = tid; o < NC; o += blockDim.x) {
        float s0 = bn_g0[o] * rsqrtf(bn_v0[o] + 1e-5f);
        g_gb0[o] = gcn_b0[o];
        g_gw0[0*NC + o] = gcn_w0[o*2 + 0];
        g_gw0[1*NC + o] = gcn_w0[o*2 + 1];
        for (int i = 0; i < NC; i++)
            for (int k = 0; k < 3; k++)
                g_tw0[(i*3 + k)*NC + o] = tcn_w0[(o*NC + i)*3 + k] * s0;
        g_tb0[o] = (tcn_b0[o] - bn_m0[o]) * s0 + bn_b0[o];

        float sr = res_bn_g[o] * rsqrtf(res_bn_v[o] + 1e-5f);
        g_rw[0*NC + o] = res_w[o*2 + 0] * sr;
        g_rw[1*NC + o] = res_w[o*2 + 1] * sr;
        g_rb[o] = (res_b[o] - res_bn_m[o]) * sr + res_bn_b[o];

        float s1 = bn_g1[o] * rsqrtf(bn_v1[o] + 1e-5f);
        g_gb1[o] = gcn_b1[o];
        for (int i = 0; i < NC; i++) g_w1[i*NC + o] = gcn_w1[o*NC + i];
        for (int i = 0; i < NC; i++)
            for (int k = 0; k < 3; k++)
                g_tw1[(i*3 + k)*NC + o] = tcn_w1[(o*NC + i)*3 + k] * s1;
        g_tb1[o] = (tcn_b1[o] - bn_m1[o]) * s1 + bn_b1[o];
    }
    for (int idx = tid; idx < FCK*NOUT; idx += blockDim.x) {
        int i = idx / NOUT, j = idx % NOUT;
        g_fcwt[idx] = fc_w[j*FCK + i];
    }
    for (int j = tid; j < NOUT; j += blockDim.x) g_fcb[j] = fc_b[j];
}

// ------------------------------- main kernel --------------------------------
__global__ __launch_bounds__(NTHR, 1)
void stgcn_kernel(const float* __restrict__ x, float* __restrict__ outp)
{
    extern __shared__ float smem[];
    float* bufA = smem + OFF_A;
    float* bufB = smem + OFF_B;
    float* As   = smem + OFF_AS;
    float* tWs  = smem + OFF_TW;
    float* W1s  = smem + OFF_W1;
    float* pp   = smem + OFF_PP;
    float* s_gw0 = pp;         // 64
    float* s_gb0 = pp + 64;    // 32
    float* s_tb0 = pp + 96;    // 32
    float* s_rw  = pp + 128;   // 64
    float* s_rb  = pp + 192;   // 32
    float* s_gb1 = pp + 224;   // 32
    float* s_tb1 = pp + 256;   // 32
    float* s_fcb = pp + 288;   // 64

    const int tid  = threadIdx.x;
    const int lane = tid & 31;
    const int wid  = tid >> 5;
    const int o    = lane;               // lane = output channel
    const int chunk = blockIdx.x;
    const int hand  = blockIdx.y;
    const int b     = blockIdx.z;
    const int t0    = chunk * TC;

    // load weights into smem
    for (int i = tid; i < NV*VP; i += NTHR) As[i] = g_A[i];
    for (int i = tid; i < NC*3*NC; i += NTHR) tWs[i] = g_tw0[i];
    for (int i = tid; i < NC*NC; i += NTHR) W1s[i] = g_w1[i];
    if (tid < 64) { s_gw0[tid] = g_gw0[tid]; s_rw[tid] = g_rw[tid]; s_fcb[tid] = g_fcb[tid]; }
    if (tid < 32) {
        s_gb0[tid] = g_gb0[tid]; s_tb0[tid] = g_tb0[tid]; s_rb[tid] = g_rb[tid];
        s_gb1[tid] = g_gb1[tid]; s_tb1[tid] = g_tb1[tid];
    }
    __syncthreads();

    // sparse structure of A (hardcoded from _CONNECTIONS, fully unrolled)
    constexpr int DEG[NV] = {6,3,3,3,2,3,3,3,2,3,3,3,2,3,3,3,2,3,3,3,2};
    constexpr int NBR[NV][6] = {
        {0,1,5,9,13,17},{0,1,2,0,0,0},{1,2,3,0,0,0},{2,3,4,0,0,0},{3,4,0,0,0,0},
        {0,5,6,0,0,0},{5,6,7,0,0,0},{6,7,8,0,0,0},{7,8,0,0,0,0},
        {0,9,10,0,0,0},{9,10,11,0,0,0},{10,11,12,0,0,0},{11,12,0,0,0,0},
        {0,13,14,0,0,0},{13,14,15,0,0,0},{14,15,16,0,0,0},{15,16,0,0,0,0},
        {0,17,18,0,0,0},{17,18,19,0,0,0},{18,19,20,0,0,0},{19,20,0,0,0,0}};

    // ---------------- Stage A: gcn0 (A-mix + 2->32 channel lift + bias) -----
    {
        const float w00 = s_gw0[o], w01 = s_gw0[NC + o];
        const float gb0 = s_gb0[o];
        for (int s = wid; s < SLOTA; s += NWARP) {
            int t = t0 + s - 2;
            float* dst = bufA + (s*NC + o)*VP;
            if (t < 0 || t >= TLEN) {
                #pragma unroll
                for (int v = 0; v < VP; v++) dst[v] = 0.f;
            } else {
                const float2* xp = (const float2*)(x + ((size_t)((b*TLEN + t)*2 + hand)*NV)*2);
                float p[NV];
                #pragma unroll
                for (int u = 0; u < NV; u++) {
                    float2 xv = xp[u];
                    p[u] = w00*xv.x + w01*xv.y;
                }
                #pragma unroll
                for (int v = 0; v < NV; v++) {
                    float acc = gb0;
                    #pragma unroll
                    for (int j = 0; j < 6; j++)
                        if (j < DEG[v]) acc += As[v*VP + NBR[v][j]] * p[NBR[v][j]];
                    dst[v] = acc;
                }
                dst[21] = 0.f;
            }
        }
    }
    __syncthreads();

    // ---------------- Stage B: tcn0 + bn0 (folded) + res0 + relu ------------
    {
        const float tb0 = s_tb0[o];
        const float rw0 = s_rw[o], rw1 = s_rw[NC + o], rb = s_rb[o];
        for (int s = wid; s < SLOTB; s += NWARP) {
            int t = t0 + s - 1;
            float* dst = bufB + (s*NC + o)*VP;
            if (t < 0 || t >= TLEN) {
                #pragma unroll
                for (int v = 0; v < VP; v++) dst[v] = 0.f;
            } else {
                float2 acc[11];
                #pragma unroll
                for (int q = 0; q < 11; q++) acc[q] = make_float2(tb0, tb0);
                for (int k = 0; k < 3; k++) {
                    const float* base = bufA + (s + k)*NC*VP;
                    for (int i = 0; i < NC; i++) {
                        float w = tWs[(i*3 + k)*NC + o];
                        const float2* row = (const float2*)(base + i*VP);
                        #pragma unroll
                        for (int q = 0; q < 11; q++) {
                            float2 h = row[q];
                            acc[q].x += w*h.x; acc[q].y += w*h.y;
                        }
                    }
                }
                const float2* xp = (const float2*)(x + ((size_t)((b*TLEN + t)*2 + hand)*NV)*2);
                #pragma unroll
                for (int q = 0; q < 11; q++) {
                    int v0 = 2*q, v1 = 2*q + 1;
                    float2 xv0 = xp[v0];
                    float r0 = rb + rw0*xv0.x + rw1*xv0.y;
                    float y0 = acc[q].x + r0;
                    dst[v0] = y0 > 0.f ? y0 : 0.f;
                    if (v1 < NV) {
                        float2 xv1 = xp[v1];
                        float r1 = rb + rw0*xv1.x + rw1*xv1.y;
                        float y1 = acc[q].y + r1;
                        dst[v1] = y1 > 0.f ? y1 : 0.f;
                    } else {
                        dst[v1] = 0.f;
                    }
                }
            }
        }
    }
    __syncthreads();

    // swap in tcn1 weights (tWs region free after stage B)
    for (int i = tid; i < NC*3*NC; i += NTHR) tWs[i] = g_tw1[i];
    __syncthreads();

    // ---------------- Stage C: gcn1 (channel mix then A-mix), into bufA -----
    {
        const float gb1 = s_gb1[o];
        for (int s = wid; s < SLOTB; s += NWARP) {
            int t = t0 + s - 1;
            float* dst = bufA + (s*NC + o)*VP;   // bufC aliases bufA
            if (t < 0 || t >= TLEN) {
                #pragma unroll
                for (int v = 0; v < VP; v++) dst[v] = 0.f;
            } else {
                float2 r2[11];
                #pragma unroll
                for (int q = 0; q < 11; q++) r2[q] = make_float2(0.f, 0.f);
                const float* base = bufB + s*NC*VP;
                for (int i = 0; i < NC; i++) {
                    float w = W1s[i*NC + o];
                    const float2* row = (const float2*)(base + i*VP);
                    #pragma unroll
                    for (int q = 0; q < 11; q++) {
                        float2 h = row[q];
                        r2[q].x += w*h.x; r2[q].y += w*h.y;
                    }
                }
                float r[VP];
                #pragma unroll
                for (int q = 0; q < 11; q++) { r[2*q] = r2[q].x; r[2*q+1] = r2[q].y; }
                #pragma unroll
                for (int v = 0; v < NV; v++) {
                    float acc = gb1;
                    #pragma unroll
                    for (int j = 0; j < 6; j++)
                        if (j < DEG[v]) acc += As[v*VP + NBR[v][j]] * r[NBR[v][j]];
                    dst[v] = acc;
                }
                dst[21] = 0.f;
            }
        }
    }
    __syncthreads();

    // ---------------- Stage D: tcn1 + bn1 (folded) + identity res + relu ----
    float dreg[2][NV];
    {
        const float tb1 = s_tb1[o];
        #pragma unroll
        for (int half = 0; half < 2; half++) {
            int s = wid + half*NWARP;           // output t = t0 + s, always valid
            float2 acc[11];
            #pragma unroll
            for (int q = 0; q < 11; q++) acc[q] = make_float2(tb1, tb1);
            for (int k = 0; k < 3; k++) {
                const float* base = bufA + (s + k)*NC*VP;
                for (int i = 0; i < NC; i++) {
                    float w = tWs[(i*3 + k)*NC + o];
                    const float2* row = (const float2*)(base + i*VP);
                    #pragma unroll
                    for (int q = 0; q < 11; q++) {
                        float2 h = row[q];
                        acc[q].x += w*h.x; acc[q].y += w*h.y;
                    }
                }
            }
            const float2* rr = (const float2*)(bufB + ((s + 1)*NC + o)*VP);
            #pragma unroll
            for (int q = 0; q < 11; q++) {
                float2 res = rr[q];
                float y0 = acc[q].x + res.x;
                dreg[half][2*q] = y0 > 0.f ? y0 : 0.f;
                if (2*q + 1 < NV) {
                    float y1 = acc[q].y + res.y;
                    dreg[half][2*q + 1] = y1 > 0.f ? y1 : 0.f;
                }
            }
        }
    }
    __syncthreads();   // all reads of bufB done -> safe to overwrite with hf
    #pragma unroll
    for (int half = 0; half < 2; half++) {
        int s = wid + half*NWARP;
        float* hf = bufB + s*FCK + o*NV;   // hf layout: [slot][c*21+v], stride 672
        #pragma unroll
        for (int v = 0; v < NV; v++) hf[v] = dreg[half][v];
    }
    __syncthreads();

    // ---------------- Stage E: fc (672 -> 64), fc_w streamed via smem -------
    {
        float a00 = 0.f, a01 = 0.f, a10 = 0.f, a11 = 0.f;
        const float* hfA = bufB + wid*FCK;
        const float* hfB = bufB + (wid + NWARP)*FCK;
        for (int c0 = 0; c0 < FCK; c0 += IC) {
            // load transposed chunk: fcs[j][ii] = fcWT[c0+ii][j]
            for (int idx = tid; idx < IC*NOUT; idx += NTHR) {
                int ii = idx >> 6, j = idx & 63;
                tWs[j*ICP + ii] = g_fcwt[(c0 + ii)*NOUT + j];
            }
            __syncthreads();
            const float4* w0p = (const float4*)(tWs + lane*ICP);
            const float4* w1p = (const float4*)(tWs + (lane + 32)*ICP);
            const float4* h0p = (const float4*)(hfA + c0);
            const float4* h1p = (const float4*)(hfB + c0);
            #pragma unroll
            for (int q = 0; q < IC/4; q++) {
                float4 wa = w0p[q], wb = w1p[q], h0 = h0p[q], h1 = h1p[q];
                a00 += wa.x*h0.x + wa.y*h0.y + wa.z*h0.z + wa.w*h0.w;
                a01 += wb.x*h0.x + wb.y*h0.y + wb.z*h0.z + wb.w*h0.w;
                a10 += wa.x*h1.x + wa.y*h1.y + wa.z*h1.z + wa.w*h1.w;
                a11 += wb.x*h1.x + wb.y*h1.y + wb.z*h1.z + wb.w*h1.w;
            }
            __syncthreads();
        }
        int ta = t0 + wid, tb_ = t0 + wid + NWARP;
        float* opa = outp + ((size_t)((b*TLEN + ta)*2 + hand))*NOUT;
        opa[lane]      = a00 + s_fcb[lane];
        opa[lane + 32] = a01 + s_fcb[lane + 32];
        float* opb = outp + ((size_t)((b*TLEN + tb_)*2 + hand))*NOUT;
        opb[lane]      = a10 + s_fcb[lane];
        opb[lane + 32] = a11 + s_fcb[lane + 32];
    }
}

// ------------------------------- launch -------------------------------------
extern "C" void kernel_launch(void* const* d_in, const int* in_sizes, int n_in,
                              void* d_out, int out_size)
{
    (void)in_sizes; (void)n_in; (void)out_size;
    const float* x = (const float*)d_in[0];

    prep_kernel<<<1, 512>>>(
        (const float*)d_in[1],  (const float*)d_in[2],
        (const float*)d_in[3],  (const float*)d_in[4],
        (const float*)d_in[5],  (const float*)d_in[6],
        (const float*)d_in[7],  (const float*)d_in[8],
        (const float*)d_in[9],  (const float*)d_in[10],
        (const float*)d_in[11], (const float*)d_in[12],
        (const float*)d_in[13], (const float*)d_in[14],
        (const float*)d_in[15], (const float*)d_in[16],
        (const float*)d_in[17], (const float*)d_in[18],
        (const float*)d_in[19], (const float*)d_in[20],
        (const float*)d_in[21], (const float*)d_in[22],
        (const float*)d_in[23], (const float*)d_in[24]);

    cudaFuncSetAttribute(stgcn_kernel,
                         cudaFuncAttributeMaxDynamicSharedMemorySize, SMEM_BYTES);
    dim3 grid(NCHUNK, 2, 64);
    stgcn_kernel<<<grid, NTHR, SMEM_BYTES>>>(x, (float*)d_out);
}

// round 4
// speedup vs baseline: 2.0481x; 2.0456x over previous
#include <cuda_runtime.h>
#include <cstddef>

// ---------------------------------------------------------------------------
// Fused 2-block ST-GCN + FC, fp32 with packed f32x2 FMA.
//   x: [64,512,2,21,2]  ->  out: [64,512,2,64]
// Folds (prep): BN into weights; tcn0*gcn_w0 -> tw0f[2ci][3k][32o];
//   tcn1*gcn_w1 -> tw1f[32i][3k][32o] with A-mix moved AFTER tcn1 (commutes);
//   gcn biases -> per-tap constants with t-boundary corrections;
//   fc_w -> zero-padded [64][768] (k' = c*24+v).
// Main: CTA = (chunk of 32 t, hand, batch), 512 thr, lane = channel.
// ---------------------------------------------------------------------------

#define TLEN 512
#define NV   21
#define VP   24
#define NC   32
#define NOUT 64
#define FKP  768
#define TC   32
#define NCHUNK 16
#define SLOTX 36
#define SLOTB 34
#define NWARP 16
#define NTHR  512
#define KC    128
#define KCP   132

// smem float offsets
#define OFF_H1  0
#define SZ_H1   (SLOTB*NC*VP)   // 26112 (reused as hf[32][768] later)
#define OFF_XD  (OFF_H1+SZ_H1)
#define SZ_XD   (SLOTX*2*VP)    // 1728
#define OFF_AX  (OFF_XD+SZ_XD)
#define SZ_AX   (SLOTX*2*VP)    // 1728
#define OFF_AS  (OFF_AX+SZ_AX)
#define SZ_AS   464
#define OFF_TW1 (OFF_AS+SZ_AS)
#define SZ_TW1  (NC*3*NC)       // 3072
#define OFF_FCS (OFF_TW1+SZ_TW1)
#define SZ_FCS  (NOUT*KCP)      // 8448
#define OFF_PP  (OFF_FCS+SZ_FCS)
#define SZ_PP   640
#define SMEM_FLOATS (OFF_PP+SZ_PP)
#define SMEM_BYTES  (SMEM_FLOATS*4)   // ~168.8 KB

// pp layout
#define PP_TW0 0      // 192  [(k*2+ci)*32+o]
#define PP_BK0 192    // 96   [k*32+o]
#define PP_BK1 288    // 96
#define PP_TB0 384    // 32
#define PP_TB1 416    // 32
#define PP_RW  448    // 64   [ci*32+o]
#define PP_RB  512    // 32
#define PP_FCB 544    // 64
#define PP_TOT 608

typedef unsigned long long u64;

__device__ __forceinline__ u64 fma2(u64 a, u64 b, u64 c) {
    u64 d; asm("fma.rn.f32x2 %0,%1,%2,%3;" : "=l"(d) : "l"(a), "l"(b), "l"(c)); return d;
}
__device__ __forceinline__ u64 dup2(float v) {
    u64 r; asm("mov.b64 %0,{%1,%1};" : "=l"(r) : "f"(v)); return r;
}
__device__ __forceinline__ float2 un2(u64 p) {
    float2 f; asm("mov.b64 {%0,%1},%2;" : "=f"(f.x), "=f"(f.y) : "l"(p)); return f;
}

// ------------------------- folded parameter storage -------------------------
__device__ float g_A[SZ_AS];
__device__ float g_tw1f[NC*3*NC];
__device__ float g_fcw2[NOUT*FKP];
__device__ float g_pp[PP_TOT];

__global__ void prep_kernel(
    const float* __restrict__ gcn_w0, const float* __restrict__ gcn_b0,
    const float* __restrict__ tcn_w0, const float* __restrict__ tcn_b0,
    const float* __restrict__ bn_g0,  const float* __restrict__ bn_b0,
    const float* __restrict__ bn_m0,  const float* __restrict__ bn_v0,
    const float* __restrict__ res_w,  const float* __restrict__ res_b,
    const float* __restrict__ res_bn_g, const float* __restrict__ res_bn_b,
    const float* __restrict__ res_bn_m, const float* __restrict__ res_bn_v,
    const float* __restrict__ gcn_w1, const float* __restrict__ gcn_b1,
    const float* __restrict__ tcn_w1, const float* __restrict__ tcn_b1,
    const float* __restrict__ bn_g1,  const float* __restrict__ bn_b1,
    const float* __restrict__ bn_m1,  const float* __restrict__ bn_v1,
    const float* __restrict__ fc_w,   const float* __restrict__ fc_b)
{
    int gtid = blockIdx.x*blockDim.x + threadIdx.x;
    int nthr = gridDim.x*blockDim.x;

    // fc transpose + zero-pad: g_fcw2[j][c*24+v]
    for (int idx = gtid; idx < NOUT*FKP; idx += nthr) {
        int j = idx / FKP, kp = idx - j*FKP;
        int c = kp / VP, v = kp - c*VP;
        g_fcw2[idx] = (v < NV) ? fc_w[j*(NC*NV) + c*NV + v] : 0.f;
    }
    // tw1f[(i*3+k)*32+o] = s1[o] * sum_j tcn_w1[o,j,k] * gcn_w1[j,i]
    for (int idx = gtid; idx < NC*3*NC; idx += nthr) {
        int o = idx & 31, ik = idx >> 5;
        int i = ik / 3, k = ik - i*3;
        float s1 = bn_g1[o] * rsqrtf(bn_v1[o] + 1e-5f);
        float s = 0.f;
        for (int j = 0; j < NC; j++)
            s += tcn_w1[(o*NC + j)*3 + k] * gcn_w1[j*NC + i];
        g_tw1f[(i*3 + k)*NC + o] = s * s1;
    }
    if (gtid == 0) {
        float Ad[NV][NV];
        for (int i = 0; i < NV; i++)
            for (int j = 0; j < NV; j++) Ad[i][j] = (i == j) ? 1.f : 0.f;
        const int conn[20][2] = {{0,1},{1,2},{2,3},{3,4},{0,5},{5,6},{6,7},{7,8},
                                 {0,9},{9,10},{10,11},{11,12},{0,13},{13,14},{14,15},
                                 {15,16},{0,17},{17,18},{18,19},{19,20}};
        for (int e = 0; e < 20; e++) {
            Ad[conn[e][0]][conn[e][1]] = 1.f;
            Ad[conn[e][1]][conn[e][0]] = 1.f;
        }
        float d[NV];
        for (int i = 0; i < NV; i++) {
            float s = 0.f;
            for (int j = 0; j < NV; j++) s += Ad[i][j];
            d[i] = rsqrtf(s);
        }
        for (int i = 0; i < SZ_AS; i++) g_A[i] = 0.f;
        for (int i = 0; i < NV; i++)
            for (int j = 0; j < NV; j++) g_A[i*22 + j] = d[i]*Ad[i][j]*d[j];
    }
    if (gtid < NC) {
        int o = gtid;
        float s0 = bn_g0[o] * rsqrtf(bn_v0[o] + 1e-5f);
        for (int k = 0; k < 3; k++) {
            for (int ci = 0; ci < 2; ci++) {
                float s = 0.f;
                for (int i = 0; i < NC; i++)
                    s += tcn_w0[(o*NC + i)*3 + k] * gcn_w0[i*2 + ci];
                g_pp[PP_TW0 + (k*2 + ci)*NC + o] = s * s0;
            }
            float sb = 0.f;
            for (int i = 0; i < NC; i++)
                sb += tcn_w0[(o*NC + i)*3 + k] * gcn_b0[i];
            g_pp[PP_BK0 + k*NC + o] = sb * s0;

            float sb1 = 0.f;
            float s1 = bn_g1[o] * rsqrtf(bn_v1[o] + 1e-5f);
            for (int j = 0; j < NC; j++)
                sb1 += tcn_w1[(o*NC + j)*3 + k] * gcn_b1[j];
            g_pp[PP_BK1 + k*NC + o] = sb1 * s1;
        }
        g_pp[PP_TB0 + o] = (tcn_b0[o] - bn_m0[o]) * s0 + bn_b0[o];
        float s1 = bn_g1[o] * rsqrtf(bn_v1[o] + 1e-5f);
        g_pp[PP_TB1 + o] = (tcn_b1[o] - bn_m1[o]) * s1 + bn_b1[o];
        float sr = res_bn_g[o] * rsqrtf(res_bn_v[o] + 1e-5f);
        g_pp[PP_RW + o]      = res_w[o*2 + 0] * sr;
        g_pp[PP_RW + NC + o] = res_w[o*2 + 1] * sr;
        g_pp[PP_RB + o] = (res_b[o] - res_bn_m[o]) * sr + res_bn_b[o];
    }
    if (gtid >= 64 && gtid < 128) g_pp[PP_FCB + gtid - 64] = fc_b[gtid - 64];
}

// ------------------------------- main kernel --------------------------------
__global__ __launch_bounds__(NTHR, 1)
void stgcn_kernel(const float* __restrict__ x, float* __restrict__ outp)
{
    extern __shared__ float smem[];
    float* bufH1 = smem + OFF_H1;
    float* bufXd = smem + OFF_XD;
    float* bufAx = smem + OFF_AX;
    float* As    = smem + OFF_AS;
    float* tw1s  = smem + OFF_TW1;
    float* fcs   = smem + OFF_FCS;
    float* pp    = smem + OFF_PP;

    const int tid  = threadIdx.x;
    const int lane = tid & 31;
    const int wid  = tid >> 5;
    const int o    = lane;
    const int t0   = blockIdx.x * TC;
    const int hand = blockIdx.y;
    const int b    = blockIdx.z;

    constexpr int DEG[NV] = {6,3,3,3,2,3,3,3,2,3,3,3,2,3,3,3,2,3,3,3,2};
    constexpr int NBR[NV][6] = {
        {0,1,5,9,13,17},{0,1,2,0,0,0},{1,2,3,0,0,0},{2,3,4,0,0,0},{3,4,0,0,0,0},
        {0,5,6,0,0,0},{5,6,7,0,0,0},{6,7,8,0,0,0},{7,8,0,0,0,0},
        {0,9,10,0,0,0},{9,10,11,0,0,0},{10,11,12,0,0,0},{11,12,0,0,0,0},
        {0,13,14,0,0,0},{13,14,15,0,0,0},{14,15,16,0,0,0},{15,16,0,0,0,0},
        {0,17,18,0,0,0},{17,18,19,0,0,0},{18,19,20,0,0,0},{19,20,0,0,0,0}};

    // ---- prolog: zero x-region, load weights ------------------------------
    {
        float4 z4 = make_float4(0.f, 0.f, 0.f, 0.f);
        float4* zp = (float4*)bufXd;
        for (int i = tid; i < (SZ_XD + SZ_AX)/4; i += NTHR) zp[i] = z4;
        for (int i = tid; i < SZ_AS; i += NTHR)   As[i]   = g_A[i];
        for (int i = tid; i < SZ_TW1; i += NTHR)  tw1s[i] = g_tw1f[i];
        for (int i = tid; i < PP_TOT; i += NTHR)  pp[i]   = g_pp[i];   // FIX: was if(tid<PP_TOT)
    }
    __syncthreads();

    // ---- fill x de-interleaved: bufXd[s][ci*24+v] -------------------------
    for (int idx = tid; idx < SLOTX*NV; idx += NTHR) {
        int s = idx / NV, v = idx - s*NV;
        int t = t0 + s - 2;
        if (t >= 0 && t < TLEN) {
            float2 xv = *(const float2*)(x + (((size_t)(b*TLEN + t)*2 + hand)*NV + v)*2);
            bufXd[s*48 + v]      = xv.x;
            bufXd[s*48 + VP + v] = xv.y;
        }
    }
    __syncthreads();

    // ---- stage A: dense A-mix of 2-ch x -> bufAx [s][ci][24] --------------
    for (int sA = wid; sA < SLOTX; sA += NWARP) {
        if (lane < VP) {
            float s0 = 0.f, s1 = 0.f;
            if (lane < NV) {
                const float* Arow = As + lane*22;
                const float* xr = bufXd + sA*48;
                #pragma unroll
                for (int u = 0; u < NV; u++) {
                    float a = Arow[u];
                    s0 += a * xr[u];
                    s1 += a * xr[VP + u];
                }
            }
            bufAx[sA*48 + lane]      = s0;
            bufAx[sA*48 + VP + lane] = s1;
        }
    }
    __syncthreads();

    // ---- stage B: folded tcn0 + bias + residual + relu -> bufH1 -----------
    {
        const float tb0  = pp[PP_TB0 + o];
        const float bk00 = pp[PP_BK0 + o];
        const float bk01 = pp[PP_BK0 + NC + o];
        const float bk02 = pp[PP_BK0 + 2*NC + o];
        const float rbv  = pp[PP_RB + o];
        const u64 rw0d = dup2(pp[PP_RW + o]);
        const u64 rw1d = dup2(pp[PP_RW + NC + o]);
        for (int sB = wid; sB < SLOTB; sB += NWARP) {
            int t = t0 + sB - 1;
            float* dst = bufH1 + ((size_t)sB*NC + o)*VP;
            if (t < 0 || t >= TLEN) {
                float4 z = make_float4(0.f, 0.f, 0.f, 0.f);
                #pragma unroll
                for (int m = 0; m < 6; m++) ((float4*)dst)[m] = z;
            } else {
                float bias = tb0 + bk00 + bk01 + bk02 + rbv;
                if (t == 0)        bias -= bk00;
                if (t == TLEN - 1) bias -= bk02;
                u64 acc[12];
                u64 bd = dup2(bias);
                #pragma unroll
                for (int q = 0; q < 12; q++) acc[q] = bd;
                #pragma unroll
                for (int k = 0; k < 3; k++) {
                    #pragma unroll
                    for (int ci = 0; ci < 2; ci++) {
                        u64 w = dup2(pp[PP_TW0 + (k*2 + ci)*NC + o]);
                        const ulonglong2* rp = (const ulonglong2*)(bufAx + (sB + k)*48 + ci*VP);
                        #pragma unroll
                        for (int m = 0; m < 6; m++) {
                            ulonglong2 r2 = rp[m];
                            acc[2*m]   = fma2(w, r2.x, acc[2*m]);
                            acc[2*m+1] = fma2(w, r2.y, acc[2*m+1]);
                        }
                    }
                }
                // residual on raw x (rb folded into bias)
                const ulonglong2* x0p = (const ulonglong2*)(bufXd + (sB + 1)*48);
                const ulonglong2* x1p = (const ulonglong2*)(bufXd + (sB + 1)*48 + VP);
                #pragma unroll
                for (int m = 0; m < 6; m++) {
                    ulonglong2 xa = x0p[m], xb = x1p[m];
                    acc[2*m]   = fma2(rw0d, xa.x, acc[2*m]);
                    acc[2*m]   = fma2(rw1d, xb.x, acc[2*m]);
                    acc[2*m+1] = fma2(rw0d, xa.y, acc[2*m+1]);
                    acc[2*m+1] = fma2(rw1d, xb.y, acc[2*m+1]);
                }
                float ov[24];
                #pragma unroll
                for (int q = 0; q < 12; q++) {
                    float2 f = un2(acc[q]);
                    ov[2*q]   = fmaxf(f.x, 0.f);
                    ov[2*q+1] = fmaxf(f.y, 0.f);
                }
                ov[21] = 0.f; ov[22] = 0.f; ov[23] = 0.f;
                #pragma unroll
                for (int m = 0; m < 6; m++)
                    ((float4*)dst)[m] = make_float4(ov[4*m], ov[4*m+1], ov[4*m+2], ov[4*m+3]);
            }
        }
    }
    __syncthreads();

    // ---- stage D: folded tcn1, then in-reg A-mix + bias + res + relu ------
    const int s0loc = 2*wid;              // output slots s0loc, s0loc+1
    u64 acc0[12], acc1[12];
    #pragma unroll
    for (int q = 0; q < 12; q++) { acc0[q] = 0ull; acc1[q] = 0ull; }
    #pragma unroll 1
    for (int i = 0; i < NC; i++) {
        const float* wp = tw1s + i*3*NC + o;
        u64 w0 = dup2(wp[0]), w1 = dup2(wp[NC]), w2 = dup2(wp[2*NC]);
        #pragma unroll
        for (int r = 0; r < 4; r++) {
            const ulonglong2* rp = (const ulonglong2*)(bufH1 + ((size_t)(s0loc + r)*NC + i)*VP);
            u64 rr[12];
            #pragma unroll
            for (int m = 0; m < 6; m++) {
                ulonglong2 r2 = rp[m];
                rr[2*m] = r2.x; rr[2*m+1] = r2.y;
            }
            if (r < 3) {
                u64 w = (r == 0) ? w0 : (r == 1) ? w1 : w2;
                #pragma unroll
                for (int q = 0; q < 12; q++) acc0[q] = fma2(w, rr[q], acc0[q]);
            }
            if (r >= 1) {
                u64 w = (r == 1) ? w0 : (r == 2) ? w1 : w2;
                #pragma unroll
                for (int q = 0; q < 12; q++) acc1[q] = fma2(w, rr[q], acc1[q]);
            }
        }
    }

    float d0[24], d1[24];
    #pragma unroll
    for (int half = 0; half < 2; half++) {
        u64* acc = half ? acc1 : acc0;
        float* dq = half ? d1 : d0;
        int s = s0loc + half;
        int t = t0 + s;
        float qv[24];
        #pragma unroll
        for (int q = 0; q < 12; q++) {
            float2 f = un2(acc[q]);
            qv[2*q] = f.x; qv[2*q+1] = f.y;
        }
        float bias = pp[PP_TB1 + o] + pp[PP_BK1 + o] + pp[PP_BK1 + NC + o] + pp[PP_BK1 + 2*NC + o];
        if (t == 0)        bias -= pp[PP_BK1 + o];
        if (t == TLEN - 1) bias -= pp[PP_BK1 + 2*NC + o];
        float rres[24];
        const float4* rp4 = (const float4*)(bufH1 + ((size_t)(s + 1)*NC + o)*VP);
        #pragma unroll
        for (int m = 0; m < 6; m++) {
            float4 f = rp4[m];
            rres[4*m] = f.x; rres[4*m+1] = f.y; rres[4*m+2] = f.z; rres[4*m+3] = f.w;
        }
        #pragma unroll
        for (int v = 0; v < NV; v++) {
            float p = bias + rres[v];
            #pragma unroll
            for (int j = 0; j < 6; j++)
                if (j < DEG[v]) p += As[v*22 + NBR[v][j]] * qv[NBR[v][j]];
            dq[v] = fmaxf(p, 0.f);
        }
        dq[21] = 0.f; dq[22] = 0.f; dq[23] = 0.f;
    }
    __syncthreads();    // all bufH1 reads done -> reuse as hf[32][768]

    {
        float* h0 = bufH1 + (size_t)s0loc*FKP + o*VP;
        float* h1 = h0 + FKP;
        #pragma unroll
        for (int m = 0; m < 6; m++) {
            ((float4*)h0)[m] = make_float4(d0[4*m], d0[4*m+1], d0[4*m+2], d0[4*m+3]);
            ((float4*)h1)[m] = make_float4(d1[4*m], d1[4*m+1], d1[4*m+2], d1[4*m+3]);
        }
    }

    // ---- stage E: fc (768p -> 64), weights streamed through smem ----------
    {
        u64 a00 = 0ull, a01 = 0ull, a10 = 0ull, a11 = 0ull;
        const float* hA = bufH1 + (size_t)s0loc*FKP;
        const float* hB = hA + FKP;
        for (int c0 = 0; c0 < FKP; c0 += KC) {
            __syncthreads();   // protect fcs from prior-iter readers
            for (int i4 = tid; i4 < NOUT*(KC/4); i4 += NTHR) {
                int j = i4 >> 5, kk4 = i4 & 31;
                ((float4*)(fcs + j*KCP))[kk4] =
                    ((const float4*)(g_fcw2 + (size_t)j*FKP + c0))[kk4];
            }
            __syncthreads();
            const ulonglong2* wa4 = (const ulonglong2*)(fcs + lane*KCP);
            const ulonglong2* wb4 = (const ulonglong2*)(fcs + (lane + 32)*KCP);
            const ulonglong2* ha4 = (const ulonglong2*)(hA + c0);
            const ulonglong2* hb4 = (const ulonglong2*)(hB + c0);
            #pragma unroll
            for (int q = 0; q < KC/4; q++) {
                ulonglong2 wa = wa4[q], wb = wb4[q], ha = ha4[q], hb = hb4[q];
                a00 = fma2(wa.x, ha.x, a00);
                a01 = fma2(wb.x, ha.x, a01);
                a10 = fma2(wa.x, hb.x, a10);
                a11 = fma2(wb.x, hb.x, a11);
                a00 = fma2(wa.y, ha.y, a00);
                a01 = fma2(wb.y, ha.y, a01);
                a10 = fma2(wa.y, hb.y, a10);
                a11 = fma2(wb.y, hb.y, a11);
            }
        }
        int ta = t0 + s0loc, tb = ta + 1;
        float fb0 = pp[PP_FCB + lane], fb1 = pp[PP_FCB + lane + 32];
        float2 r;
        float* opa = outp + ((size_t)((b*TLEN + ta)*2 + hand))*NOUT;
        float* opb = outp + ((size_t)((b*TLEN + tb)*2 + hand))*NOUT;
        r = un2(a00); opa[lane]      = r.x + r.y + fb0;
        r = un2(a01); opa[lane + 32] = r.x + r.y + fb1;
        r = un2(a10); opb[lane]      = r.x + r.y + fb0;
        r = un2(a11); opb[lane + 32] = r.x + r.y + fb1;
    }
}

// ------------------------------- launch -------------------------------------
extern "C" void kernel_launch(void* const* d_in, const int* in_sizes, int n_in,
                              void* d_out, int out_size)
{
    (void)in_sizes; (void)n_in; (void)out_size;
    const float* x = (const float*)d_in[0];

    prep_kernel<<<48, 256>>>(
        (const float*)d_in[1],  (const float*)d_in[2],
        (const float*)d_in[3],  (const float*)d_in[4],
        (const float*)d_in[5],  (const float*)d_in[6],
        (const float*)d_in[7],  (const float*)d_in[8],
        (const float*)d_in[9],  (const float*)d_in[10],
        (const float*)d_in[11], (const float*)d_in[12],
        (const float*)d_in[13], (const float*)d_in[14],
        (const float*)d_in[15], (const float*)d_in[16],
        (const float*)d_in[17], (const float*)d_in[18],
        (const float*)d_in[19], (const float*)d_in[20],
        (const float*)d_in[21], (const float*)d_in[22],
        (const float*)d_in[23], (const float*)d_in[24]);

    cudaFuncSetAttribute(stgcn_kernel,
                         cudaFuncAttributeMaxDynamicSharedMemorySize, SMEM_BYTES);
    dim3 grid(NCHUNK, 2, 64);
    stgcn_kernel<<<grid, NTHR, SMEM_BYTES>>>(x, (float*)d_out);
}